// round 2
// baseline (speedup 1.0000x reference)
#include <cuda_runtime.h>
#include <cuda_bf16.h>
#include <math_constants.h>

// Problem dims
#define BATCH 8
#define SEQ   2048
#define WIDTH 768
#define HEAD  64
#define MROWS (BATCH * SEQ)   // 16384

// Scratch for Q, K, V (scale folded into Q)
__device__ float g_Q[MROWS * HEAD];
__device__ float g_K[MROWS * HEAD];
__device__ float g_V[MROWS * HEAD];

typedef unsigned long long ull;

// ---- packed f32x2 helpers (Blackwell FFMA2 path, PTX-only) ----
__device__ __forceinline__ ull pkdup(float x) {
    ull r;
    asm("mov.b64 %0, {%1, %1};" : "=l"(r) : "f"(x));
    return r;
}
__device__ __forceinline__ float2 upk2(ull v) {
    float2 r;
    asm("mov.b64 {%0, %1}, %2;" : "=f"(r.x), "=f"(r.y) : "l"(v));
    return r;
}
__device__ __forceinline__ void fma2(ull& d, ull a, ull b) {
    asm("fma.rn.f32x2 %0, %1, %2, %3;" : "=l"(d) : "l"(a), "l"(b), "l"(d));
}
__device__ __forceinline__ void mul2(ull& d, ull a, ull b) {
    asm("mul.rn.f32x2 %0, %1, %2;" : "=l"(d) : "l"(a), "l"(b));
}

// ---------------------------------------------------------------------------
// Kernel 1: fused QKV projection.
// C[M=16384, 192] = x[M, 768] @ [Wq|Wk|Wv][768, 192] + bias
// 64x192 block tile, 256 threads, 4x12 register tile, FFMA2 inner loop.
// ---------------------------------------------------------------------------
__global__ __launch_bounds__(256) void qkv_kernel(
    const float* __restrict__ x,
    const float* __restrict__ Wq, const float* __restrict__ bq,
    const float* __restrict__ Wk, const float* __restrict__ bk,
    const float* __restrict__ Wv, const float* __restrict__ bv)
{
    __shared__ float xs[64 * 33];    // 64 rows x 32 k, pad 33
    __shared__ float ws[32 * 192];   // 32 k x 192 cols  (16B-aligned base: 2112*4)

    const int tid = threadIdx.x;
    const int ty = tid >> 4;         // 0..15
    const int tx = tid & 15;         // 0..15
    const int block_row = blockIdx.x * 64;

    ull acc[4][6];                   // 4 rows x 12 cols as 6 f32x2 pairs
#pragma unroll
    for (int i = 0; i < 4; ++i)
#pragma unroll
        for (int j = 0; j < 6; ++j) acc[i][j] = 0ull;

    for (int kk = 0; kk < WIDTH; kk += 32) {
        // load x tile: 64x32
#pragma unroll
        for (int t = 0; t < 8; ++t) {
            int i = t * 256 + tid;
            int r = i >> 5, c = i & 31;
            xs[r * 33 + c] = x[(size_t)(block_row + r) * WIDTH + kk + c];
        }
        // load W tile: 32 x 192 (Wq | Wk | Wv)
#pragma unroll
        for (int t = 0; t < 8; ++t) {
            int i = t * 256 + tid;
            int k = i >> 6, h = i & 63;
            int gk = (kk + k) * HEAD + h;
            ws[k * 192 + h]       = Wq[gk];
            ws[k * 192 + 64 + h]  = Wk[gk];
            ws[k * 192 + 128 + h] = Wv[gk];
        }
        __syncthreads();

#pragma unroll
        for (int k = 0; k < 32; ++k) {
            const float* wrow = &ws[k * 192 + tx * 12];
            ulonglong2 wa = *(const ulonglong2*)(wrow);      // cols 0..3
            ulonglong2 wb = *(const ulonglong2*)(wrow + 4);  // cols 4..7
            ulonglong2 wc = *(const ulonglong2*)(wrow + 8);  // cols 8..11
#pragma unroll
            for (int i = 0; i < 4; ++i) {
                ull xv = pkdup(xs[(ty * 4 + i) * 33 + k]);
                fma2(acc[i][0], xv, wa.x);
                fma2(acc[i][1], xv, wa.y);
                fma2(acc[i][2], xv, wb.x);
                fma2(acc[i][3], xv, wb.y);
                fma2(acc[i][4], xv, wc.x);
                fma2(acc[i][5], xv, wc.y);
            }
        }
        __syncthreads();
    }

    const float scale = 0.125f;  // 1/sqrt(64), folded into Q
#pragma unroll
    for (int i = 0; i < 4; ++i) {
        int row = block_row + ty * 4 + i;
#pragma unroll
        for (int j = 0; j < 6; ++j) {
            float2 v2 = upk2(acc[i][j]);
            float vv[2] = {v2.x, v2.y};
#pragma unroll
            for (int u = 0; u < 2; ++u) {
                int col = tx * 12 + j * 2 + u;
                float v = vv[u];
                if (col < 64) {
                    g_Q[(size_t)row * HEAD + col] = (v + bq[col]) * scale;
                } else if (col < 128) {
                    g_K[(size_t)row * HEAD + (col - 64)] = v + bk[col - 64];
                } else {
                    g_V[(size_t)row * HEAD + (col - 128)] = v + bv[col - 128];
                }
            }
        }
    }
}

// ---------------------------------------------------------------------------
// Kernel 2: flash-style attention, Br = Bc = 64, FFMA2 inner loops.
// grid (SEQ/64, BATCH), 256 threads. Thread (ty,tx): rows ty*4..+4, cols tx*4..+4.
// smem (floats):
//   qst [64(h)][68]  Q transposed, XOR row-swizzle by ((h>>3)&3)*4
//   kst [64(h)][68]  K transposed, same swizzle
//   vs  [64][64]     V tile
//   ps  [64][68]     P tile row-major (float4 stores)
//   msb [128 u32]    mask bits
// ---------------------------------------------------------------------------
#define ATTN_SMEM_BYTES 69120

__global__ __launch_bounds__(256) void attn_kernel(
    const int* __restrict__ mask, float* __restrict__ out)
{
    extern __shared__ float sm[];
    float* qst = sm;                    // 64*68 = 4352
    float* kst = sm + 4352;             // 64*68 = 4352
    float* vs  = sm + 8704;             // 64*64 = 4096
    float* ps  = sm + 12800;            // 64*68 = 4352
    unsigned* msb = (unsigned*)(sm + 17152); // 128 words

    const int tid = threadIdx.x;
    const int ty = tid >> 4;
    const int tx = tid & 15;
    const int b  = blockIdx.y;
    const int q0 = blockIdx.x * 64;

    // load Q tile transposed with swizzle (conflict-free stores)
#pragma unroll
    for (int t = 0; t < 16; ++t) {
        int i = t * 256 + tid;
        int r = i >> 6, h = i & 63;
        int sw = ((h >> 3) & 3) * 4;
        qst[h * 68 + (r ^ sw)] = g_Q[((size_t)(b * SEQ + q0 + r)) * HEAD + h];
    }

    ull acc[4][2];
    float m[4], l[4];
#pragma unroll
    for (int i = 0; i < 4; ++i) {
        m[i] = -1e30f; l[i] = 0.0f;
        acc[i][0] = 0ull; acc[i][1] = 0ull;
    }

    const int row_sw = ((ty * 4) /* ^ sw applied per h below */);

    for (int k0 = 0; k0 < SEQ; k0 += 64) {
        __syncthreads();  // prior iteration done reading ps/vs

        // load K transposed (swizzled), V row-major
#pragma unroll
        for (int t = 0; t < 16; ++t) {
            int i = t * 256 + tid;
            int r = i >> 6, h = i & 63;
            int sw = ((h >> 3) & 3) * 4;
            size_t g = ((size_t)(b * SEQ + k0 + r)) * HEAD + h;
            kst[h * 68 + (r ^ sw)] = g_K[g];
            vs[r * 64 + h]         = g_V[g];
        }
        // load + bitpack mask chunk
#pragma unroll
        for (int t = 0; t < 16; ++t) {
            int i = t * 256 + tid;
            int r = i >> 6, c = i & 63;
            int mv = mask[(size_t)(q0 + r) * SEQ + k0 + c];
            unsigned bal = __ballot_sync(0xffffffffu, mv != 0);
            if ((tid & 31) == 0) msb[r * 2 + (c >> 5)] = bal;
        }
        __syncthreads();

        // S = Q @ K^T  (scale already folded into Q), packed f32x2
        ull s2[4][2];
#pragma unroll
        for (int i = 0; i < 4; ++i) { s2[i][0] = 0ull; s2[i][1] = 0ull; }

#pragma unroll 8
        for (int h = 0; h < 64; ++h) {
            int sw = ((h >> 3) & 3) * 4;
            ulonglong2 kv = *(const ulonglong2*)&kst[h * 68 + ((tx * 4) ^ sw)];
            float4 qv = *(const float4*)&qst[h * 68 + ((ty * 4) ^ sw)];
            ull q0d = pkdup(qv.x), q1d = pkdup(qv.y);
            ull q2d = pkdup(qv.z), q3d = pkdup(qv.w);
            fma2(s2[0][0], q0d, kv.x); fma2(s2[0][1], q0d, kv.y);
            fma2(s2[1][0], q1d, kv.x); fma2(s2[1][1], q1d, kv.y);
            fma2(s2[2][0], q2d, kv.x); fma2(s2[2][1], q2d, kv.y);
            fma2(s2[3][0], q3d, kv.x); fma2(s2[3][1], q3d, kv.y);
        }

        // mask + online softmax
#pragma unroll
        for (int i = 0; i < 4; ++i) {
            int row = ty * 4 + i;
            float2 sa = upk2(s2[i][0]);
            float2 sb = upk2(s2[i][1]);
            float s[4] = {sa.x, sa.y, sb.x, sb.y};

            unsigned w = msb[row * 2 + (tx >> 3)];
            float rmax = -1e30f;
#pragma unroll
            for (int j = 0; j < 4; ++j) {
                int c = tx * 4 + j;
                bool keep = (w >> (c & 31)) & 1u;
                s[j] = keep ? s[j] : -1e30f;
                rmax = fmaxf(rmax, s[j]);
            }
#pragma unroll
            for (int o = 8; o >= 1; o >>= 1)
                rmax = fmaxf(rmax, __shfl_xor_sync(0xffffffffu, rmax, o));

            float mnew = fmaxf(m[i], rmax);
            float corr = __expf(m[i] - mnew);
            float p[4];
            float rsum = 0.0f;
#pragma unroll
            for (int j = 0; j < 4; ++j) {
                p[j] = __expf(s[j] - mnew);
                rsum += p[j];
            }
            // vector store of the P row chunk
            float4 p4; p4.x = p[0]; p4.y = p[1]; p4.z = p[2]; p4.w = p[3];
            *(float4*)&ps[row * 68 + tx * 4] = p4;

#pragma unroll
            for (int o = 8; o >= 1; o >>= 1)
                rsum += __shfl_xor_sync(0xffffffffu, rsum, o);

            l[i] = l[i] * corr + rsum;
            m[i] = mnew;
            ull c2 = pkdup(corr);
            mul2(acc[i][0], acc[i][0], c2);
            mul2(acc[i][1], acc[i][1], c2);
        }
        __syncthreads();  // ps complete

        // O += P @ V, packed f32x2
#pragma unroll 8
        for (int kc = 0; kc < 64; ++kc) {
            ulonglong2 vv = *(const ulonglong2*)&vs[kc * 64 + tx * 4];
            ull p0 = pkdup(ps[(ty * 4 + 0) * 68 + kc]);
            ull p1 = pkdup(ps[(ty * 4 + 1) * 68 + kc]);
            ull p2 = pkdup(ps[(ty * 4 + 2) * 68 + kc]);
            ull p3 = pkdup(ps[(ty * 4 + 3) * 68 + kc]);
            fma2(acc[0][0], p0, vv.x); fma2(acc[0][1], p0, vv.y);
            fma2(acc[1][0], p1, vv.x); fma2(acc[1][1], p1, vv.y);
            fma2(acc[2][0], p2, vv.x); fma2(acc[2][1], p2, vv.y);
            fma2(acc[3][0], p3, vv.x); fma2(acc[3][1], p3, vv.y);
        }
    }

    // write O = acc / l
#pragma unroll
    for (int i = 0; i < 4; ++i) {
        float inv = 1.0f / l[i];
        ull i2 = pkdup(inv);
        ull o0 = acc[i][0], o1 = acc[i][1];
        mul2(o0, o0, i2);
        mul2(o1, o1, i2);
        float2 oa = upk2(o0), ob = upk2(o1);
        float4 o4; o4.x = oa.x; o4.y = oa.y; o4.z = ob.x; o4.w = ob.y;
        size_t row = (size_t)(b * SEQ + q0 + ty * 4 + i);
        *(float4*)&out[row * HEAD + tx * 4] = o4;
    }
    (void)row_sw;
}

// ---------------------------------------------------------------------------
extern "C" void kernel_launch(void* const* d_in, const int* in_sizes, int n_in,
                              void* d_out, int out_size)
{
    const float* x  = (const float*)d_in[0];
    const float* Wq = (const float*)d_in[1];
    const float* bq = (const float*)d_in[2];
    const float* Wk = (const float*)d_in[3];
    const float* bk = (const float*)d_in[4];
    const float* Wv = (const float*)d_in[5];
    const float* bv = (const float*)d_in[6];
    const int* mask = (const int*)d_in[7];
    float* out = (float*)d_out;

    cudaFuncSetAttribute(attn_kernel,
                         cudaFuncAttributeMaxDynamicSharedMemorySize,
                         ATTN_SMEM_BYTES);

    qkv_kernel<<<MROWS / 64, 256>>>(x, Wq, bq, Wk, bk, Wv, bv);
    attn_kernel<<<dim3(SEQ / 64, BATCH), 256, ATTN_SMEM_BYTES>>>(mask, out);
}

// round 3
// speedup vs baseline: 2.3530x; 2.3530x over previous
#include <cuda_runtime.h>
#include <cuda_bf16.h>

#define BATCH 8
#define SEQ   2048
#define WIDTH 768
#define HEAD  64
#define MROWS (BATCH * SEQ)   // 16384

// Q/K/V stored as split bf16 (value = hi + lo), scale 1/8 folded into Q
__device__ __align__(16) __nv_bfloat16 g_Qh[MROWS * HEAD];
__device__ __align__(16) __nv_bfloat16 g_Ql[MROWS * HEAD];
__device__ __align__(16) __nv_bfloat16 g_Kh[MROWS * HEAD];
__device__ __align__(16) __nv_bfloat16 g_Kl[MROWS * HEAD];
__device__ __align__(16) __nv_bfloat16 g_Vh[MROWS * HEAD];
__device__ __align__(16) __nv_bfloat16 g_Vl[MROWS * HEAD];
__device__ __align__(16) unsigned g_maskbits[SEQ * (SEQ / 32)];  // 512KB bit mask

// ---------------- PTX helpers ----------------
__device__ __forceinline__ unsigned saddr(const void* p) {
    return (unsigned)__cvta_generic_to_shared(p);
}
__device__ __forceinline__ void ldm_x4(unsigned& r0, unsigned& r1, unsigned& r2,
                                       unsigned& r3, unsigned a) {
    asm volatile("ldmatrix.sync.aligned.m8n8.x4.shared.b16 {%0,%1,%2,%3}, [%4];"
                 : "=r"(r0), "=r"(r1), "=r"(r2), "=r"(r3) : "r"(a));
}
__device__ __forceinline__ void ldm_x2(unsigned& r0, unsigned& r1, unsigned a) {
    asm volatile("ldmatrix.sync.aligned.m8n8.x2.shared.b16 {%0,%1}, [%2];"
                 : "=r"(r0), "=r"(r1) : "r"(a));
}
__device__ __forceinline__ void ldm_x2t(unsigned& r0, unsigned& r1, unsigned a) {
    asm volatile("ldmatrix.sync.aligned.m8n8.x2.trans.shared.b16 {%0,%1}, [%2];"
                 : "=r"(r0), "=r"(r1) : "r"(a));
}
__device__ __forceinline__ void mma_bf16(float c[4], const unsigned a[4],
                                         unsigned b0, unsigned b1) {
    asm volatile(
        "mma.sync.aligned.m16n8k16.row.col.f32.bf16.bf16.f32 "
        "{%0,%1,%2,%3}, {%4,%5,%6,%7}, {%8,%9}, {%0,%1,%2,%3};"
        : "+f"(c[0]), "+f"(c[1]), "+f"(c[2]), "+f"(c[3])
        : "r"(a[0]), "r"(a[1]), "r"(a[2]), "r"(a[3]), "r"(b0), "r"(b1));
}
// split a,b (fp32) into bf16 hi-pair and lo-pair packed as u32 {low=a, high=b}
__device__ __forceinline__ void split_pack(float a, float b, unsigned& hi, unsigned& lo) {
    __nv_bfloat16 ha = __float2bfloat16(a), hb = __float2bfloat16(b);
    __nv_bfloat16 la = __float2bfloat16(a - __bfloat162float(ha));
    __nv_bfloat16 lb = __float2bfloat16(b - __bfloat162float(hb));
    __nv_bfloat162 vh = __halves2bfloat162(ha, hb);
    __nv_bfloat162 vl = __halves2bfloat162(la, lb);
    hi = *reinterpret_cast<unsigned*>(&vh);
    lo = *reinterpret_cast<unsigned*>(&vl);
}
__device__ __forceinline__ void split_store(float a, float b,
                                            __nv_bfloat16* ph, __nv_bfloat16* pl) {
    unsigned hi, lo;
    split_pack(a, b, hi, lo);
    *reinterpret_cast<unsigned*>(ph) = hi;
    *reinterpret_cast<unsigned*>(pl) = lo;
}

// ---------------------------------------------------------------------------
// Kernel 0: bit-pack the mask (2048x2048 int -> 2048x64 u32)
// ---------------------------------------------------------------------------
__global__ __launch_bounds__(256) void mask_pack_kernel(const int* __restrict__ mask) {
    int row = blockIdx.x;
    int w = threadIdx.x >> 5;
    int lane = threadIdx.x & 31;
    for (int i = w; i < 64; i += 8) {
        int c = i * 32 + lane;
        unsigned bal = __ballot_sync(0xffffffffu, mask[(size_t)row * SEQ + c] != 0);
        if (lane == 0) g_maskbits[row * 64 + i] = bal;
    }
}

// ---------------------------------------------------------------------------
// Kernel 1: QKV projection, bf16 3-split mma.sync.
// C[16384,192] = x[16384,768] @ [Wq|Wk|Wv] + bias; stores split bf16.
// 256 thr (8 warps, 2m x 4n), CTA tile 64x192, warp tile 32x48, k-chunk 32.
// ---------------------------------------------------------------------------
__global__ __launch_bounds__(256) void qkv_kernel(
    const float* __restrict__ x,
    const float* __restrict__ Wq, const float* __restrict__ bq,
    const float* __restrict__ Wk, const float* __restrict__ bk,
    const float* __restrict__ Wv, const float* __restrict__ bv)
{
    __shared__ __nv_bfloat16 xs_h[64][40], xs_l[64][40];     // A tile (row-major)
    __shared__ __nv_bfloat16 ws_h[32][200], ws_l[32][200];   // B tile [k][n]

    const int tid = threadIdx.x;
    const int lane = tid & 31;
    const int warp = tid >> 5;
    const int wm = warp >> 2;   // 0..1
    const int wn = warp & 3;    // 0..3
    const int block_row = blockIdx.x * 64;

    float acc[2][6][4];
#pragma unroll
    for (int mi = 0; mi < 2; ++mi)
#pragma unroll
        for (int j = 0; j < 6; ++j)
#pragma unroll
            for (int r = 0; r < 4; ++r) acc[mi][j][r] = 0.0f;

    const int a_r = (lane & 7) + ((lane & 8) ? 8 : 0);   // A x4 row
    const int a_k8 = (lane & 16) ? 8 : 0;                // A x4 k offset
    const int bt_r = (lane & 7) + ((lane & 8) ? 8 : 0);  // trans-x2 row (k dim)

    for (int kk = 0; kk < WIDTH; kk += 32) {
        // load x tile 64x32 fp32 -> split bf16
#pragma unroll
        for (int i = 0; i < 2; ++i) {
            int f = tid + i * 256;           // 0..511 float4 slots
            int r = f >> 3, c4 = (f & 7) * 4;
            float4 v = *(const float4*)&x[(size_t)(block_row + r) * WIDTH + kk + c4];
            split_store(v.x, v.y, &xs_h[r][c4], &xs_l[r][c4]);
            split_store(v.z, v.w, &xs_h[r][c4 + 2], &xs_l[r][c4 + 2]);
        }
        // load W tile 32x192 (Wq|Wk|Wv) -> split bf16
#pragma unroll
        for (int i = 0; i < 6; ++i) {
            int f = tid + i * 256;           // 0..1535 float4 slots
            int k = f / 48;
            int nq = (f % 48) * 4;           // global n col
            const float* src = (nq < 64) ? Wq : (nq < 128) ? Wk : Wv;
            int col = nq & 63;
            float4 v = *(const float4*)&src[(size_t)(kk + k) * HEAD + col];
            split_store(v.x, v.y, &ws_h[k][nq], &ws_l[k][nq]);
            split_store(v.z, v.w, &ws_h[k][nq + 2], &ws_l[k][nq + 2]);
        }
        __syncthreads();

#pragma unroll
        for (int u = 0; u < 2; ++u) {
            int k0 = u * 16;
            unsigned ah[2][4], al[2][4];
#pragma unroll
            for (int mi = 0; mi < 2; ++mi) {
                int row = wm * 32 + mi * 16 + a_r;
                ldm_x4(ah[mi][0], ah[mi][1], ah[mi][2], ah[mi][3],
                       saddr(&xs_h[row][k0 + a_k8]));
                ldm_x4(al[mi][0], al[mi][1], al[mi][2], al[mi][3],
                       saddr(&xs_l[row][k0 + a_k8]));
            }
#pragma unroll
            for (int j = 0; j < 6; ++j) {
                int n0 = wn * 48 + j * 8;
                unsigned bh0, bh1, bl0, bl1;
                ldm_x2t(bh0, bh1, saddr(&ws_h[k0 + bt_r][n0]));
                ldm_x2t(bl0, bl1, saddr(&ws_l[k0 + bt_r][n0]));
#pragma unroll
                for (int mi = 0; mi < 2; ++mi) {
                    mma_bf16(acc[mi][j], ah[mi], bh0, bh1);
                    mma_bf16(acc[mi][j], ah[mi], bl0, bl1);
                    mma_bf16(acc[mi][j], al[mi], bh0, bh1);
                }
            }
        }
        __syncthreads();
    }

    // epilogue: bias, Q scale, split bf16 store
#pragma unroll
    for (int mi = 0; mi < 2; ++mi) {
#pragma unroll
        for (int j = 0; j < 6; ++j) {
            int col = wn * 48 + j * 8 + (lane & 3) * 2;
            int r0 = block_row + wm * 32 + mi * 16 + (lane >> 2);
#pragma unroll
            for (int half = 0; half < 2; ++half) {
                int row = r0 + half * 8;
                float a = acc[mi][j][half * 2 + 0];
                float b = acc[mi][j][half * 2 + 1];
                if (col < 64) {
                    a = (a + bq[col]) * 0.125f;
                    b = (b + bq[col + 1]) * 0.125f;
                    size_t base = (size_t)row * HEAD + col;
                    split_store(a, b, &g_Qh[base], &g_Ql[base]);
                } else if (col < 128) {
                    a += bk[col - 64];
                    b += bk[col - 63];
                    size_t base = (size_t)row * HEAD + col - 64;
                    split_store(a, b, &g_Kh[base], &g_Kl[base]);
                } else {
                    a += bv[col - 128];
                    b += bv[col - 127];
                    size_t base = (size_t)row * HEAD + col - 128;
                    split_store(a, b, &g_Vh[base], &g_Vl[base]);
                }
            }
        }
    }
}

// ---------------------------------------------------------------------------
// Kernel 2: flash attention, bf16 3-split mma.sync.
// CTA: 64 q-rows, 4 warps (warp = 16 rows). Key tile Bc=64.
// ---------------------------------------------------------------------------
#define ATTN_SMEM 55296   // 6 tiles of 64x72 bf16

__global__ __launch_bounds__(128) void attn_kernel(float* __restrict__ out)
{
    extern __shared__ __nv_bfloat16 smem[];
    __nv_bfloat16* qs_h = smem;              // [64][72]
    __nv_bfloat16* qs_l = smem + 4608;
    __nv_bfloat16* ks_h = smem + 9216;
    __nv_bfloat16* ks_l = smem + 13824;
    __nv_bfloat16* vs_h = smem + 18432;
    __nv_bfloat16* vs_l = smem + 23040;

    const int tid = threadIdx.x;
    const int lane = tid & 31, warp = tid >> 5;
    const int b = blockIdx.y, q0 = blockIdx.x * 64;
    const float NEG_INF = __int_as_float(0xff800000);

    // load Q tile (split bf16, 16B vectors)
#pragma unroll
    for (int i = 0; i < 4; ++i) {
        int f = tid + i * 128;
        int r = f >> 3, c8 = (f & 7) * 8;
        size_t g = ((size_t)(b * SEQ + q0 + r)) * HEAD + c8;
        *(uint4*)&qs_h[r * 72 + c8] = *(const uint4*)&g_Qh[g];
        *(uint4*)&qs_l[r * 72 + c8] = *(const uint4*)&g_Ql[g];
    }

    float o[8][4];
#pragma unroll
    for (int j = 0; j < 8; ++j)
#pragma unroll
        for (int r = 0; r < 4; ++r) o[j][r] = 0.0f;
    float m_lo = -1e30f, m_hi = -1e30f, l_lo = 0.0f, l_hi = 0.0f;

    const int a_r = warp * 16 + (lane & 7) + ((lane & 8) ? 8 : 0);  // Q x4 row
    const int a_k8 = (lane & 16) ? 8 : 0;
    const int bn_r = lane & 7;                      // non-trans x2: row within n-tile
    const int bn_c8 = (lane & 8) ? 8 : 0;           // non-trans x2: k offset
    const int bt_r = (lane & 7) + ((lane & 8) ? 8 : 0);  // trans x2 row (k dim)
    const int grl = q0 + warp * 16 + (lane >> 2);   // global q row (lo)

    for (int k0 = 0; k0 < SEQ; k0 += 64) {
        __syncthreads();
        // load K,V tiles (split bf16)
#pragma unroll
        for (int i = 0; i < 4; ++i) {
            int f = tid + i * 128;
            int r = f >> 3, c8 = (f & 7) * 8;
            size_t g = ((size_t)(b * SEQ + k0 + r)) * HEAD + c8;
            *(uint4*)&ks_h[r * 72 + c8] = *(const uint4*)&g_Kh[g];
            *(uint4*)&ks_l[r * 72 + c8] = *(const uint4*)&g_Kl[g];
            *(uint4*)&vs_h[r * 72 + c8] = *(const uint4*)&g_Vh[g];
            *(uint4*)&vs_l[r * 72 + c8] = *(const uint4*)&g_Vl[g];
        }
        __syncthreads();

        // ---- S = Q @ K^T (3-split) ----
        float s[8][4];
#pragma unroll
        for (int j = 0; j < 8; ++j)
#pragma unroll
            for (int r = 0; r < 4; ++r) s[j][r] = 0.0f;

#pragma unroll
        for (int u = 0; u < 4; ++u) {
            unsigned qh[4], ql[4];
            ldm_x4(qh[0], qh[1], qh[2], qh[3], saddr(&qs_h[a_r * 72 + u * 16 + a_k8]));
            ldm_x4(ql[0], ql[1], ql[2], ql[3], saddr(&qs_l[a_r * 72 + u * 16 + a_k8]));
#pragma unroll
            for (int j = 0; j < 8; ++j) {
                unsigned bh0, bh1, bl0, bl1;
                ldm_x2(bh0, bh1, saddr(&ks_h[(j * 8 + bn_r) * 72 + u * 16 + bn_c8]));
                ldm_x2(bl0, bl1, saddr(&ks_l[(j * 8 + bn_r) * 72 + u * 16 + bn_c8]));
                mma_bf16(s[j], qh, bh0, bh1);
                mma_bf16(s[j], qh, bl0, bl1);
                mma_bf16(s[j], ql, bh0, bh1);
            }
        }

        // ---- mask + online softmax ----
        unsigned long long mw_lo =
            *(const unsigned long long*)&g_maskbits[(size_t)grl * 64 + (k0 >> 5)];
        unsigned long long mw_hi =
            *(const unsigned long long*)&g_maskbits[(size_t)(grl + 8) * 64 + (k0 >> 5)];
        float rmax_lo = NEG_INF, rmax_hi = NEG_INF;
#pragma unroll
        for (int j = 0; j < 8; ++j) {
            int cb = j * 8 + (lane & 3) * 2;
            s[j][0] = ((mw_lo >> cb) & 1ull) ? s[j][0] : NEG_INF;
            s[j][1] = ((mw_lo >> (cb + 1)) & 1ull) ? s[j][1] : NEG_INF;
            s[j][2] = ((mw_hi >> cb) & 1ull) ? s[j][2] : NEG_INF;
            s[j][3] = ((mw_hi >> (cb + 1)) & 1ull) ? s[j][3] : NEG_INF;
            rmax_lo = fmaxf(rmax_lo, fmaxf(s[j][0], s[j][1]));
            rmax_hi = fmaxf(rmax_hi, fmaxf(s[j][2], s[j][3]));
        }
        rmax_lo = fmaxf(rmax_lo, __shfl_xor_sync(0xffffffffu, rmax_lo, 1));
        rmax_lo = fmaxf(rmax_lo, __shfl_xor_sync(0xffffffffu, rmax_lo, 2));
        rmax_hi = fmaxf(rmax_hi, __shfl_xor_sync(0xffffffffu, rmax_hi, 1));
        rmax_hi = fmaxf(rmax_hi, __shfl_xor_sync(0xffffffffu, rmax_hi, 2));

        float mnew_lo = fmaxf(m_lo, rmax_lo);
        float mnew_hi = fmaxf(m_hi, rmax_hi);
        float corr_lo = __expf(m_lo - mnew_lo);
        float corr_hi = __expf(m_hi - mnew_hi);
        float sum_lo = 0.0f, sum_hi = 0.0f;
#pragma unroll
        for (int j = 0; j < 8; ++j) {
            s[j][0] = __expf(s[j][0] - mnew_lo);
            s[j][1] = __expf(s[j][1] - mnew_lo);
            s[j][2] = __expf(s[j][2] - mnew_hi);
            s[j][3] = __expf(s[j][3] - mnew_hi);
            sum_lo += s[j][0] + s[j][1];
            sum_hi += s[j][2] + s[j][3];
        }
        sum_lo += __shfl_xor_sync(0xffffffffu, sum_lo, 1);
        sum_lo += __shfl_xor_sync(0xffffffffu, sum_lo, 2);
        sum_hi += __shfl_xor_sync(0xffffffffu, sum_hi, 1);
        sum_hi += __shfl_xor_sync(0xffffffffu, sum_hi, 2);

        l_lo = l_lo * corr_lo + sum_lo;  m_lo = mnew_lo;
        l_hi = l_hi * corr_hi + sum_hi;  m_hi = mnew_hi;
#pragma unroll
        for (int j = 0; j < 8; ++j) {
            o[j][0] *= corr_lo; o[j][1] *= corr_lo;
            o[j][2] *= corr_hi; o[j][3] *= corr_hi;
        }

        // ---- O += P @ V (3-split); P frags built from S regs ----
#pragma unroll
        for (int u = 0; u < 4; ++u) {
            unsigned pah[4], pal[4];
            split_pack(s[2 * u][0],     s[2 * u][1],     pah[0], pal[0]);
            split_pack(s[2 * u][2],     s[2 * u][3],     pah[1], pal[1]);
            split_pack(s[2 * u + 1][0], s[2 * u + 1][1], pah[2], pal[2]);
            split_pack(s[2 * u + 1][2], s[2 * u + 1][3], pah[3], pal[3]);
#pragma unroll
            for (int j = 0; j < 8; ++j) {
                unsigned bh0, bh1, bl0, bl1;
                ldm_x2t(bh0, bh1, saddr(&vs_h[(u * 16 + bt_r) * 72 + j * 8]));
                ldm_x2t(bl0, bl1, saddr(&vs_l[(u * 16 + bt_r) * 72 + j * 8]));
                mma_bf16(o[j], pah, bh0, bh1);
                mma_bf16(o[j], pah, bl0, bl1);
                mma_bf16(o[j], pal, bh0, bh1);
            }
        }
    }

    // epilogue: O /= l
    float inv_lo = 1.0f / l_lo, inv_hi = 1.0f / l_hi;
#pragma unroll
    for (int j = 0; j < 8; ++j) {
        int col = j * 8 + (lane & 3) * 2;
        size_t r0 = (size_t)b * SEQ + grl;
        float2 v0 = {o[j][0] * inv_lo, o[j][1] * inv_lo};
        float2 v1 = {o[j][2] * inv_hi, o[j][3] * inv_hi};
        *(float2*)&out[r0 * HEAD + col] = v0;
        *(float2*)&out[(r0 + 8) * HEAD + col] = v1;
    }
}

// ---------------------------------------------------------------------------
extern "C" void kernel_launch(void* const* d_in, const int* in_sizes, int n_in,
                              void* d_out, int out_size)
{
    const float* x  = (const float*)d_in[0];
    const float* Wq = (const float*)d_in[1];
    const float* bq = (const float*)d_in[2];
    const float* Wk = (const float*)d_in[3];
    const float* bk = (const float*)d_in[4];
    const float* Wv = (const float*)d_in[5];
    const float* bv = (const float*)d_in[6];
    const int* mask = (const int*)d_in[7];
    float* out = (float*)d_out;

    cudaFuncSetAttribute(attn_kernel,
                         cudaFuncAttributeMaxDynamicSharedMemorySize, ATTN_SMEM);

    mask_pack_kernel<<<SEQ, 256>>>(mask);
    qkv_kernel<<<MROWS / 64, 256>>>(x, Wq, bq, Wk, bk, Wv, bv);
    attn_kernel<<<dim3(SEQ / 64, BATCH), 128, ATTN_SMEM>>>(out);
}

// round 4
// speedup vs baseline: 3.1127x; 1.3229x over previous
#include <cuda_runtime.h>
#include <cuda_fp16.h>

#define BATCH 8
#define SEQ   2048
#define WIDTH 768
#define HEAD  64
#define MROWS (BATCH * SEQ)   // 16384

// Q/K/V stored as split fp16 (value = hi + lo), scale 1/8 folded into Q
__device__ __align__(16) __half g_Qh[MROWS * HEAD];
__device__ __align__(16) __half g_Ql[MROWS * HEAD];
__device__ __align__(16) __half g_Kh[MROWS * HEAD];
__device__ __align__(16) __half g_Kl[MROWS * HEAD];
__device__ __align__(16) __half g_Vh[MROWS * HEAD];
__device__ __align__(16) __half g_Vl[MROWS * HEAD];
__device__ __align__(16) unsigned g_maskbits[SEQ * (SEQ / 32)];  // 512KB bit mask

// ---------------- PTX helpers ----------------
__device__ __forceinline__ unsigned saddr(const void* p) {
    return (unsigned)__cvta_generic_to_shared(p);
}
__device__ __forceinline__ void ldm_x4(unsigned& r0, unsigned& r1, unsigned& r2,
                                       unsigned& r3, unsigned a) {
    asm volatile("ldmatrix.sync.aligned.m8n8.x4.shared.b16 {%0,%1,%2,%3}, [%4];"
                 : "=r"(r0), "=r"(r1), "=r"(r2), "=r"(r3) : "r"(a));
}
__device__ __forceinline__ void ldm_x2(unsigned& r0, unsigned& r1, unsigned a) {
    asm volatile("ldmatrix.sync.aligned.m8n8.x2.shared.b16 {%0,%1}, [%2];"
                 : "=r"(r0), "=r"(r1) : "r"(a));
}
__device__ __forceinline__ void ldm_x2t(unsigned& r0, unsigned& r1, unsigned a) {
    asm volatile("ldmatrix.sync.aligned.m8n8.x2.trans.shared.b16 {%0,%1}, [%2];"
                 : "=r"(r0), "=r"(r1) : "r"(a));
}
__device__ __forceinline__ void mma_f16(float c[4], const unsigned a[4],
                                        unsigned b0, unsigned b1) {
    asm volatile(
        "mma.sync.aligned.m16n8k16.row.col.f32.f16.f16.f32 "
        "{%0,%1,%2,%3}, {%4,%5,%6,%7}, {%8,%9}, {%0,%1,%2,%3};"
        : "+f"(c[0]), "+f"(c[1]), "+f"(c[2]), "+f"(c[3])
        : "r"(a[0]), "r"(a[1]), "r"(a[2]), "r"(a[3]), "r"(b0), "r"(b1));
}
__device__ __forceinline__ void cpa16(unsigned d, const void* s) {
    asm volatile("cp.async.cg.shared.global [%0], [%1], 16;" :: "r"(d), "l"(s));
}
__device__ __forceinline__ void cp_commit() {
    asm volatile("cp.async.commit_group;");
}
template <int N>
__device__ __forceinline__ void cp_wait() {
    asm volatile("cp.async.wait_group %0;" :: "n"(N));
}

// split a,b (fp32) -> fp16 hi-pair + lo-pair, each packed as u32 {low=a, high=b}
__device__ __forceinline__ void split_pack(float a, float b, unsigned& hi, unsigned& lo) {
    __half ha = __float2half_rn(a), hb = __float2half_rn(b);
    __half la = __float2half_rn(a - __half2float(ha));
    __half lb = __float2half_rn(b - __half2float(hb));
    __half2 vh = __halves2half2(ha, hb);
    __half2 vl = __halves2half2(la, lb);
    hi = *reinterpret_cast<unsigned*>(&vh);
    lo = *reinterpret_cast<unsigned*>(&vl);
}
__device__ __forceinline__ void split_store(float a, float b, __half* ph, __half* pl) {
    unsigned hi, lo;
    split_pack(a, b, hi, lo);
    *reinterpret_cast<unsigned*>(ph) = hi;
    *reinterpret_cast<unsigned*>(pl) = lo;
}
__device__ __forceinline__ unsigned pack_h2(float a, float b) {
    __half2 v = __floats2half2_rn(a, b);
    return *reinterpret_cast<unsigned*>(&v);
}

// ---------------------------------------------------------------------------
// Kernel 0: bit-pack the mask. int4 loads + shfl-OR pack.
// ---------------------------------------------------------------------------
__global__ __launch_bounds__(256) void mask_pack_kernel(const int* __restrict__ mask) {
    int row = blockIdx.x;
    int warp = threadIdx.x >> 5, lane = threadIdx.x & 31;
#pragma unroll
    for (int seg = warp; seg < 16; seg += 8) {          // 128-col segment
        const int4 v = *(const int4*)&mask[(size_t)row * SEQ + seg * 128 + lane * 4];
        unsigned nib = (v.x != 0) | ((v.y != 0) << 1) | ((v.z != 0) << 2) | ((v.w != 0) << 3);
        unsigned word = nib << (4 * (lane & 7));
        word |= __shfl_xor_sync(0xffffffffu, word, 1);
        word |= __shfl_xor_sync(0xffffffffu, word, 2);
        word |= __shfl_xor_sync(0xffffffffu, word, 4);
        if ((lane & 7) == 0)
            g_maskbits[row * 64 + seg * 4 + (lane >> 3)] = word;
    }
}

// ---------------------------------------------------------------------------
// Kernel 1: QKV projection, fp16 2-split (3 MMAs) mma.sync.
// C[16384,192] = x[16384,768] @ [Wq|Wk|Wv] + bias; stores split fp16.
// ---------------------------------------------------------------------------
__global__ __launch_bounds__(256) void qkv_kernel(
    const float* __restrict__ x,
    const float* __restrict__ Wq, const float* __restrict__ bq,
    const float* __restrict__ Wk, const float* __restrict__ bk,
    const float* __restrict__ Wv, const float* __restrict__ bv)
{
    __shared__ __half xs_h[64][40], xs_l[64][40];     // A tile (row-major)
    __shared__ __half ws_h[32][200], ws_l[32][200];   // B tile [k][n]

    const int tid = threadIdx.x;
    const int lane = tid & 31;
    const int warp = tid >> 5;
    const int wm = warp >> 2;   // 0..1
    const int wn = warp & 3;    // 0..3
    const int block_row = blockIdx.x * 64;

    float acc[2][6][4];
#pragma unroll
    for (int mi = 0; mi < 2; ++mi)
#pragma unroll
        for (int j = 0; j < 6; ++j)
#pragma unroll
            for (int r = 0; r < 4; ++r) acc[mi][j][r] = 0.0f;

    const int a_r = (lane & 7) + ((lane & 8) ? 8 : 0);
    const int a_k8 = (lane & 16) ? 8 : 0;
    const int bt_r = (lane & 7) + ((lane & 8) ? 8 : 0);

    for (int kk = 0; kk < WIDTH; kk += 32) {
        // load x tile 64x32 fp32 -> split fp16
#pragma unroll
        for (int i = 0; i < 2; ++i) {
            int f = tid + i * 256;
            int r = f >> 3, c4 = (f & 7) * 4;
            float4 v = *(const float4*)&x[(size_t)(block_row + r) * WIDTH + kk + c4];
            split_store(v.x, v.y, &xs_h[r][c4], &xs_l[r][c4]);
            split_store(v.z, v.w, &xs_h[r][c4 + 2], &xs_l[r][c4 + 2]);
        }
        // load W tile 32x192 (Wq|Wk|Wv) -> split fp16
#pragma unroll
        for (int i = 0; i < 6; ++i) {
            int f = tid + i * 256;
            int k = f / 48;
            int nq = (f % 48) * 4;
            const float* src = (nq < 64) ? Wq : (nq < 128) ? Wk : Wv;
            int col = nq & 63;
            float4 v = *(const float4*)&src[(size_t)(kk + k) * HEAD + col];
            split_store(v.x, v.y, &ws_h[k][nq], &ws_l[k][nq]);
            split_store(v.z, v.w, &ws_h[k][nq + 2], &ws_l[k][nq + 2]);
        }
        __syncthreads();

#pragma unroll
        for (int u = 0; u < 2; ++u) {
            int k0 = u * 16;
            unsigned ah[2][4], al[2][4];
#pragma unroll
            for (int mi = 0; mi < 2; ++mi) {
                int row = wm * 32 + mi * 16 + a_r;
                ldm_x4(ah[mi][0], ah[mi][1], ah[mi][2], ah[mi][3],
                       saddr(&xs_h[row][k0 + a_k8]));
                ldm_x4(al[mi][0], al[mi][1], al[mi][2], al[mi][3],
                       saddr(&xs_l[row][k0 + a_k8]));
            }
#pragma unroll
            for (int j = 0; j < 6; ++j) {
                int n0 = wn * 48 + j * 8;
                unsigned bh0, bh1, bl0, bl1;
                ldm_x2t(bh0, bh1, saddr(&ws_h[k0 + bt_r][n0]));
                ldm_x2t(bl0, bl1, saddr(&ws_l[k0 + bt_r][n0]));
#pragma unroll
                for (int mi = 0; mi < 2; ++mi) {
                    mma_f16(acc[mi][j], ah[mi], bh0, bh1);
                    mma_f16(acc[mi][j], ah[mi], bl0, bl1);
                    mma_f16(acc[mi][j], al[mi], bh0, bh1);
                }
            }
        }
        __syncthreads();
    }

    // epilogue: bias, Q scale, split fp16 store
#pragma unroll
    for (int mi = 0; mi < 2; ++mi) {
#pragma unroll
        for (int j = 0; j < 6; ++j) {
            int col = wn * 48 + j * 8 + (lane & 3) * 2;
            int r0 = block_row + wm * 32 + mi * 16 + (lane >> 2);
#pragma unroll
            for (int half = 0; half < 2; ++half) {
                int row = r0 + half * 8;
                float a = acc[mi][j][half * 2 + 0];
                float b = acc[mi][j][half * 2 + 1];
                if (col < 64) {
                    a = (a + bq[col]) * 0.125f;
                    b = (b + bq[col + 1]) * 0.125f;
                    size_t base = (size_t)row * HEAD + col;
                    split_store(a, b, &g_Qh[base], &g_Ql[base]);
                } else if (col < 128) {
                    a += bk[col - 64];
                    b += bk[col - 63];
                    size_t base = (size_t)row * HEAD + col - 64;
                    split_store(a, b, &g_Kh[base], &g_Kl[base]);
                } else {
                    a += bv[col - 128];
                    b += bv[col - 127];
                    size_t base = (size_t)row * HEAD + col - 128;
                    split_store(a, b, &g_Vh[base], &g_Vl[base]);
                }
            }
        }
    }
}

// ---------------------------------------------------------------------------
// Kernel 2: flash attention. 128 q-rows/CTA, 8 warps, cp.async double-buffered
// K/V, fp16 split: S = 3 MMAs, PV = 2 MMAs (P hi-only).
// smem halves (stride 72 per row):
//   qs_h[128][72] qs_l[128][72]; K/V: 8 buffers of [64][72]
// ---------------------------------------------------------------------------
#define ATTN_SMEM 110592
#define NTILES (SEQ / 64)

__global__ __launch_bounds__(256) void attn_kernel(float* __restrict__ out)
{
    extern __shared__ __half smem[];
    __half* qs_h = smem;                 // 128*72 = 9216
    __half* qs_l = smem + 9216;
    __half* kv = smem + 18432;           // 8 x 4608: kh0,kh1,kl0,kl1,vh0,vh1,vl0,vl1

    const int tid = threadIdx.x;
    const int lane = tid & 31, warp = tid >> 5;
    const int b = blockIdx.y, q0 = blockIdx.x * 128;
    const float NEG_INF = __int_as_float(0xff800000);

    // Q tile via cp.async (2 arrays x 128 rows x 8 chunks)
#pragma unroll
    for (int i = 0; i < 8; ++i) {
        int f = tid + (i & 3) * 256;
        int r = f >> 3, c8 = (f & 7) * 8;
        size_t g = ((size_t)(b * SEQ + q0 + r)) * HEAD + c8;
        if (i < 4) cpa16(saddr(qs_h + r * 72 + c8), g_Qh + g);
        else       cpa16(saddr(qs_l + r * 72 + c8), g_Ql + g);
    }
    // K/V tile 0
    {
        const __half* gs[4] = {g_Kh, g_Kl, g_Vh, g_Vl};
#pragma unroll
        for (int i = 0; i < 8; ++i) {
            int arr = i >> 1;
            int f = tid + (i & 1) * 256;
            int r = f >> 3, c8 = (f & 7) * 8;
            size_t g = ((size_t)(b * SEQ + r)) * HEAD + c8;
            cpa16(saddr(kv + arr * 9216 + r * 72 + c8), gs[arr] + g);
        }
    }
    cp_commit();

    float o[8][4];
#pragma unroll
    for (int j = 0; j < 8; ++j)
#pragma unroll
        for (int r = 0; r < 4; ++r) o[j][r] = 0.0f;
    float m_lo = -1e30f, m_hi = -1e30f, l_lo = 0.0f, l_hi = 0.0f;

    const int a_r = warp * 16 + (lane & 7) + ((lane & 8) ? 8 : 0);
    const int a_k8 = (lane & 16) ? 8 : 0;
    const int bn_r = lane & 7;
    const int bn_c8 = (lane & 8) ? 8 : 0;
    const int bt_r = (lane & 7) + ((lane & 8) ? 8 : 0);
    const int grl = q0 + warp * 16 + (lane >> 2);

    for (int t = 0; t < NTILES; ++t) {
        const int buf = t & 1;
        __half* ks_h = kv + buf * 4608;
        __half* ks_l = kv + 9216 + buf * 4608;
        __half* vs_h = kv + 18432 + buf * 4608;
        __half* vs_l = kv + 27648 + buf * 4608;

        __syncthreads();   // everyone done reading buf^1 (iter t-1)
        if (t + 1 < NTILES) {
            const __half* gs[4] = {g_Kh, g_Kl, g_Vh, g_Vl};
            int nb = buf ^ 1;
#pragma unroll
            for (int i = 0; i < 8; ++i) {
                int arr = i >> 1;
                int f = tid + (i & 1) * 256;
                int r = f >> 3, c8 = (f & 7) * 8;
                size_t g = ((size_t)(b * SEQ + (t + 1) * 64 + r)) * HEAD + c8;
                cpa16(saddr(kv + arr * 9216 + nb * 4608 + r * 72 + c8), gs[arr] + g);
            }
            cp_commit();
            cp_wait<1>();
        } else {
            cp_wait<0>();
        }
        __syncthreads();   // tile t visible to all

        // ---- S = Q @ K^T (3 MMAs per step) ----
        float s[8][4];
#pragma unroll
        for (int j = 0; j < 8; ++j)
#pragma unroll
            for (int r = 0; r < 4; ++r) s[j][r] = 0.0f;

#pragma unroll
        for (int u = 0; u < 4; ++u) {
            unsigned qh[4], ql[4];
            ldm_x4(qh[0], qh[1], qh[2], qh[3], saddr(&qs_h[a_r * 72 + u * 16 + a_k8]));
            ldm_x4(ql[0], ql[1], ql[2], ql[3], saddr(&qs_l[a_r * 72 + u * 16 + a_k8]));
#pragma unroll
            for (int j = 0; j < 8; ++j) {
                unsigned bh0, bh1, bl0, bl1;
                ldm_x2(bh0, bh1, saddr(&ks_h[(j * 8 + bn_r) * 72 + u * 16 + bn_c8]));
                ldm_x2(bl0, bl1, saddr(&ks_l[(j * 8 + bn_r) * 72 + u * 16 + bn_c8]));
                mma_f16(s[j], qh, bh0, bh1);
                mma_f16(s[j], qh, bl0, bl1);
                mma_f16(s[j], ql, bh0, bh1);
            }
        }

        // ---- mask + online softmax ----
        const int k0 = t * 64;
        unsigned long long mw_lo =
            *(const unsigned long long*)&g_maskbits[(size_t)grl * 64 + (k0 >> 5)];
        unsigned long long mw_hi =
            *(const unsigned long long*)&g_maskbits[(size_t)(grl + 8) * 64 + (k0 >> 5)];
        float rmax_lo = NEG_INF, rmax_hi = NEG_INF;
#pragma unroll
        for (int j = 0; j < 8; ++j) {
            int cb = j * 8 + (lane & 3) * 2;
            s[j][0] = ((mw_lo >> cb) & 1ull) ? s[j][0] : NEG_INF;
            s[j][1] = ((mw_lo >> (cb + 1)) & 1ull) ? s[j][1] : NEG_INF;
            s[j][2] = ((mw_hi >> cb) & 1ull) ? s[j][2] : NEG_INF;
            s[j][3] = ((mw_hi >> (cb + 1)) & 1ull) ? s[j][3] : NEG_INF;
            rmax_lo = fmaxf(rmax_lo, fmaxf(s[j][0], s[j][1]));
            rmax_hi = fmaxf(rmax_hi, fmaxf(s[j][2], s[j][3]));
        }
        rmax_lo = fmaxf(rmax_lo, __shfl_xor_sync(0xffffffffu, rmax_lo, 1));
        rmax_lo = fmaxf(rmax_lo, __shfl_xor_sync(0xffffffffu, rmax_lo, 2));
        rmax_hi = fmaxf(rmax_hi, __shfl_xor_sync(0xffffffffu, rmax_hi, 1));
        rmax_hi = fmaxf(rmax_hi, __shfl_xor_sync(0xffffffffu, rmax_hi, 2));

        float mnew_lo = fmaxf(m_lo, rmax_lo);
        float mnew_hi = fmaxf(m_hi, rmax_hi);
        float corr_lo = __expf(m_lo - mnew_lo);
        float corr_hi = __expf(m_hi - mnew_hi);
        float sum_lo = 0.0f, sum_hi = 0.0f;
#pragma unroll
        for (int j = 0; j < 8; ++j) {
            s[j][0] = __expf(s[j][0] - mnew_lo);
            s[j][1] = __expf(s[j][1] - mnew_lo);
            s[j][2] = __expf(s[j][2] - mnew_hi);
            s[j][3] = __expf(s[j][3] - mnew_hi);
            sum_lo += s[j][0] + s[j][1];
            sum_hi += s[j][2] + s[j][3];
        }
        sum_lo += __shfl_xor_sync(0xffffffffu, sum_lo, 1);
        sum_lo += __shfl_xor_sync(0xffffffffu, sum_lo, 2);
        sum_hi += __shfl_xor_sync(0xffffffffu, sum_hi, 1);
        sum_hi += __shfl_xor_sync(0xffffffffu, sum_hi, 2);

        l_lo = l_lo * corr_lo + sum_lo;  m_lo = mnew_lo;
        l_hi = l_hi * corr_hi + sum_hi;  m_hi = mnew_hi;
#pragma unroll
        for (int j = 0; j < 8; ++j) {
            o[j][0] *= corr_lo; o[j][1] *= corr_lo;
            o[j][2] *= corr_hi; o[j][3] *= corr_hi;
        }

        // ---- O += P @ V (2 MMAs per step, P hi-only fp16) ----
#pragma unroll
        for (int u = 0; u < 4; ++u) {
            unsigned pa[4];
            pa[0] = pack_h2(s[2 * u][0],     s[2 * u][1]);
            pa[1] = pack_h2(s[2 * u][2],     s[2 * u][3]);
            pa[2] = pack_h2(s[2 * u + 1][0], s[2 * u + 1][1]);
            pa[3] = pack_h2(s[2 * u + 1][2], s[2 * u + 1][3]);
#pragma unroll
            for (int j = 0; j < 8; ++j) {
                unsigned bh0, bh1, bl0, bl1;
                ldm_x2t(bh0, bh1, saddr(&vs_h[(u * 16 + bt_r) * 72 + j * 8]));
                ldm_x2t(bl0, bl1, saddr(&vs_l[(u * 16 + bt_r) * 72 + j * 8]));
                mma_f16(o[j], pa, bh0, bh1);
                mma_f16(o[j], pa, bl0, bl1);
            }
        }
    }

    // epilogue: O /= l
    float inv_lo = 1.0f / l_lo, inv_hi = 1.0f / l_hi;
#pragma unroll
    for (int j = 0; j < 8; ++j) {
        int col = j * 8 + (lane & 3) * 2;
        size_t r0 = (size_t)b * SEQ + grl;
        float2 v0 = {o[j][0] * inv_lo, o[j][1] * inv_lo};
        float2 v1 = {o[j][2] * inv_hi, o[j][3] * inv_hi};
        *(float2*)&out[r0 * HEAD + col] = v0;
        *(float2*)&out[(r0 + 8) * HEAD + col] = v1;
    }
}

// ---------------------------------------------------------------------------
extern "C" void kernel_launch(void* const* d_in, const int* in_sizes, int n_in,
                              void* d_out, int out_size)
{
    const float* x  = (const float*)d_in[0];
    const float* Wq = (const float*)d_in[1];
    const float* bq = (const float*)d_in[2];
    const float* Wk = (const float*)d_in[3];
    const float* bk = (const float*)d_in[4];
    const float* Wv = (const float*)d_in[5];
    const float* bv = (const float*)d_in[6];
    const int* mask = (const int*)d_in[7];
    float* out = (float*)d_out;

    cudaFuncSetAttribute(attn_kernel,
                         cudaFuncAttributeMaxDynamicSharedMemorySize, ATTN_SMEM);

    mask_pack_kernel<<<SEQ, 256>>>(mask);
    qkv_kernel<<<MROWS / 64, 256>>>(x, Wq, bq, Wk, bk, Wv, bv);
    attn_kernel<<<dim3(SEQ / 128, BATCH), 256, ATTN_SMEM>>>(out);
}

// round 5
// speedup vs baseline: 3.7433x; 1.2026x over previous
#include <cuda_runtime.h>
#include <cuda_fp16.h>

#define BATCH 8
#define SEQ   2048
#define WIDTH 768
#define HEAD  64
#define MROWS (BATCH * SEQ)   // 16384
#define QKV_CTAS (MROWS / 64) // 256
#define MASK_CTAS 32
#define LOG2E 1.4426950408889634f

// Q/K stored as split fp16 (value = hi + lo), V as plain fp16; 1/8 folded into Q
__device__ __align__(16) __half g_Qh[MROWS * HEAD];
__device__ __align__(16) __half g_Ql[MROWS * HEAD];
__device__ __align__(16) __half g_Kh[MROWS * HEAD];
__device__ __align__(16) __half g_Kl[MROWS * HEAD];
__device__ __align__(16) __half g_Vh[MROWS * HEAD];
__device__ __align__(16) unsigned g_maskbits[SEQ * (SEQ / 32)];

// ---------------- PTX helpers ----------------
__device__ __forceinline__ unsigned saddr(const void* p) {
    return (unsigned)__cvta_generic_to_shared(p);
}
__device__ __forceinline__ void ldm_x4(unsigned& r0, unsigned& r1, unsigned& r2,
                                       unsigned& r3, unsigned a) {
    asm volatile("ldmatrix.sync.aligned.m8n8.x4.shared.b16 {%0,%1,%2,%3}, [%4];"
                 : "=r"(r0), "=r"(r1), "=r"(r2), "=r"(r3) : "r"(a));
}
__device__ __forceinline__ void ldm_x4t(unsigned& r0, unsigned& r1, unsigned& r2,
                                        unsigned& r3, unsigned a) {
    asm volatile("ldmatrix.sync.aligned.m8n8.x4.trans.shared.b16 {%0,%1,%2,%3}, [%4];"
                 : "=r"(r0), "=r"(r1), "=r"(r2), "=r"(r3) : "r"(a));
}
__device__ __forceinline__ void ldm_x2t(unsigned& r0, unsigned& r1, unsigned a) {
    asm volatile("ldmatrix.sync.aligned.m8n8.x2.trans.shared.b16 {%0,%1}, [%2];"
                 : "=r"(r0), "=r"(r1) : "r"(a));
}
__device__ __forceinline__ void mma_f16(float c[4], const unsigned a[4],
                                        unsigned b0, unsigned b1) {
    asm volatile(
        "mma.sync.aligned.m16n8k16.row.col.f32.f16.f16.f32 "
        "{%0,%1,%2,%3}, {%4,%5,%6,%7}, {%8,%9}, {%0,%1,%2,%3};"
        : "+f"(c[0]), "+f"(c[1]), "+f"(c[2]), "+f"(c[3])
        : "r"(a[0]), "r"(a[1]), "r"(a[2]), "r"(a[3]), "r"(b0), "r"(b1));
}
__device__ __forceinline__ void cpa16(unsigned d, const void* s) {
    asm volatile("cp.async.cg.shared.global [%0], [%1], 16;" :: "r"(d), "l"(s));
}
__device__ __forceinline__ void cp_commit() {
    asm volatile("cp.async.commit_group;");
}
template <int N>
__device__ __forceinline__ void cp_wait() {
    asm volatile("cp.async.wait_group %0;" :: "n"(N));
}
// p = ex2(f16x2(t1, t0)) : packs {lo=t0, hi=t1} then ex2 both halves
__device__ __forceinline__ unsigned exp2_pack(float t0, float t1) {
    unsigned h, p;
    asm("cvt.rn.f16x2.f32 %0, %1, %2;" : "=r"(h) : "f"(t1), "f"(t0));
    asm("ex2.approx.f16x2 %0, %1;" : "=r"(p) : "r"(h));
    return p;
}
__device__ __forceinline__ void split_pack(float a, float b, unsigned& hi, unsigned& lo) {
    __half ha = __float2half_rn(a), hb = __float2half_rn(b);
    __half la = __float2half_rn(a - __half2float(ha));
    __half lb = __float2half_rn(b - __half2float(hb));
    __half2 vh = __halves2half2(ha, hb);
    __half2 vl = __halves2half2(la, lb);
    hi = *reinterpret_cast<unsigned*>(&vh);
    lo = *reinterpret_cast<unsigned*>(&vl);
}
__device__ __forceinline__ void split_store(float a, float b, __half* ph, __half* pl) {
    unsigned hi, lo;
    split_pack(a, b, hi, lo);
    *reinterpret_cast<unsigned*>(ph) = hi;
    *reinterpret_cast<unsigned*>(pl) = lo;
}
__device__ __forceinline__ unsigned pack_h2(float a, float b) {
    __half2 v = __floats2half2_rn(a, b);
    return *reinterpret_cast<unsigned*>(&v);
}

// ---------------------------------------------------------------------------
// Kernel 1: fused QKV projection + mask bit-pack (tail CTAs).
// ---------------------------------------------------------------------------
__global__ __launch_bounds__(256) void qkv_mask_kernel(
    const float* __restrict__ x,
    const float* __restrict__ Wq, const float* __restrict__ bq,
    const float* __restrict__ Wk, const float* __restrict__ bk,
    const float* __restrict__ Wv, const float* __restrict__ bv,
    const int* __restrict__ mask)
{
    const int tid = threadIdx.x;
    const int lane = tid & 31;
    const int warp = tid >> 5;

    if (blockIdx.x >= QKV_CTAS) {
        // ---- mask packing: 64 rows per CTA ----
        int base_row = (blockIdx.x - QKV_CTAS) * 64;
        for (int rr = 0; rr < 64; ++rr) {
            int row = base_row + rr;
#pragma unroll
            for (int seg = warp; seg < 16; seg += 8) {
                const int4 v = *(const int4*)&mask[(size_t)row * SEQ + seg * 128 + lane * 4];
                unsigned nib = (v.x != 0) | ((v.y != 0) << 1) |
                               ((v.z != 0) << 2) | ((v.w != 0) << 3);
                unsigned word = nib << (4 * (lane & 7));
                word |= __shfl_xor_sync(0xffffffffu, word, 1);
                word |= __shfl_xor_sync(0xffffffffu, word, 2);
                word |= __shfl_xor_sync(0xffffffffu, word, 4);
                if ((lane & 7) == 0)
                    g_maskbits[row * 64 + seg * 4 + (lane >> 3)] = word;
            }
        }
        return;
    }

    __shared__ __half xs_h[64][40], xs_l[64][40];
    __shared__ __half ws_h[32][200], ws_l[32][200];

    const int wm = warp >> 2;   // 0..1
    const int wn = warp & 3;    // 0..3
    const int block_row = blockIdx.x * 64;

    float acc[2][6][4];
#pragma unroll
    for (int mi = 0; mi < 2; ++mi)
#pragma unroll
        for (int j = 0; j < 6; ++j)
#pragma unroll
            for (int r = 0; r < 4; ++r) acc[mi][j][r] = 0.0f;

    const int a_r = (lane & 7) + ((lane & 8) ? 8 : 0);
    const int a_k8 = (lane & 16) ? 8 : 0;
    const int bt_r = (lane & 7) + ((lane & 8) ? 8 : 0);

    for (int kk = 0; kk < WIDTH; kk += 32) {
#pragma unroll
        for (int i = 0; i < 2; ++i) {
            int f = tid + i * 256;
            int r = f >> 3, c4 = (f & 7) * 4;
            float4 v = *(const float4*)&x[(size_t)(block_row + r) * WIDTH + kk + c4];
            split_store(v.x, v.y, &xs_h[r][c4], &xs_l[r][c4]);
            split_store(v.z, v.w, &xs_h[r][c4 + 2], &xs_l[r][c4 + 2]);
        }
#pragma unroll
        for (int i = 0; i < 6; ++i) {
            int f = tid + i * 256;
            int k = f / 48;
            int nq = (f % 48) * 4;
            const float* src = (nq < 64) ? Wq : (nq < 128) ? Wk : Wv;
            int col = nq & 63;
            float4 v = *(const float4*)&src[(size_t)(kk + k) * HEAD + col];
            split_store(v.x, v.y, &ws_h[k][nq], &ws_l[k][nq]);
            split_store(v.z, v.w, &ws_h[k][nq + 2], &ws_l[k][nq + 2]);
        }
        __syncthreads();

#pragma unroll
        for (int u = 0; u < 2; ++u) {
            int k0 = u * 16;
            unsigned ah[2][4], al[2][4];
#pragma unroll
            for (int mi = 0; mi < 2; ++mi) {
                int row = wm * 32 + mi * 16 + a_r;
                ldm_x4(ah[mi][0], ah[mi][1], ah[mi][2], ah[mi][3],
                       saddr(&xs_h[row][k0 + a_k8]));
                ldm_x4(al[mi][0], al[mi][1], al[mi][2], al[mi][3],
                       saddr(&xs_l[row][k0 + a_k8]));
            }
#pragma unroll
            for (int j = 0; j < 6; ++j) {
                int n0 = wn * 48 + j * 8;
                unsigned bh0, bh1, bl0, bl1;
                ldm_x2t(bh0, bh1, saddr(&ws_h[k0 + bt_r][n0]));
                ldm_x2t(bl0, bl1, saddr(&ws_l[k0 + bt_r][n0]));
#pragma unroll
                for (int mi = 0; mi < 2; ++mi) {
                    mma_f16(acc[mi][j], ah[mi], bh0, bh1);
                    mma_f16(acc[mi][j], ah[mi], bl0, bl1);
                    mma_f16(acc[mi][j], al[mi], bh0, bh1);
                }
            }
        }
        __syncthreads();
    }

#pragma unroll
    for (int mi = 0; mi < 2; ++mi) {
#pragma unroll
        for (int j = 0; j < 6; ++j) {
            int col = wn * 48 + j * 8 + (lane & 3) * 2;
            int r0 = block_row + wm * 32 + mi * 16 + (lane >> 2);
#pragma unroll
            for (int half = 0; half < 2; ++half) {
                int row = r0 + half * 8;
                float a = acc[mi][j][half * 2 + 0];
                float b = acc[mi][j][half * 2 + 1];
                if (col < 64) {
                    a = (a + bq[col]) * 0.125f;
                    b = (b + bq[col + 1]) * 0.125f;
                    size_t base = (size_t)row * HEAD + col;
                    split_store(a, b, &g_Qh[base], &g_Ql[base]);
                } else if (col < 128) {
                    a += bk[col - 64];
                    b += bk[col - 63];
                    size_t base = (size_t)row * HEAD + col - 64;
                    split_store(a, b, &g_Kh[base], &g_Kl[base]);
                } else {
                    a += bv[col - 128];
                    b += bv[col - 127];
                    size_t base = (size_t)row * HEAD + col - 128;
                    *reinterpret_cast<unsigned*>(&g_Vh[base]) = pack_h2(a, b);
                }
            }
        }
    }
}

// ---------------------------------------------------------------------------
// Kernel 2: flash attention. 128 q-rows/CTA, 8 warps, cp.async double-buffered
// K (split) + V (fp16), S = 3 MMAs, PV = 1 MMA, l via ones-MMA, fp16x2 exp.
// smem halves (stride 72/row): qs_h[128][72] qs_l[128][72];
// kv: kh0,kh1,kl0,kl1,vh0,vh1 each [64][72]
// ---------------------------------------------------------------------------
#define ATTN_SMEM 92160
#define NTILES (SEQ / 64)
#define ONESF16 0x3C003C00u

__global__ __launch_bounds__(256) void attn_kernel(float* __restrict__ out)
{
    extern __shared__ __half smem[];
    __half* qs_h = smem;                 // 128*72 halves
    __half* qs_l = smem + 9216;
    __half* kv = smem + 18432;           // 6 x 4608 halves

    const int tid = threadIdx.x;
    const int lane = tid & 31, warp = tid >> 5;
    const int b = blockIdx.y, q0 = blockIdx.x * 128;
    const float NEG_INF = __int_as_float(0xff800000);

    // Q tile via cp.async
#pragma unroll
    for (int i = 0; i < 8; ++i) {
        int f = tid + (i & 3) * 256;
        int r = f >> 3, c8 = (f & 7) * 8;
        size_t g = ((size_t)(b * SEQ + q0 + r)) * HEAD + c8;
        if (i < 4) cpa16(saddr(qs_h + r * 72 + c8), g_Qh + g);
        else       cpa16(saddr(qs_l + r * 72 + c8), g_Ql + g);
    }
    // K/V tile 0
    {
        const __half* gs[3] = {g_Kh, g_Kl, g_Vh};
#pragma unroll
        for (int i = 0; i < 6; ++i) {
            int arr = i >> 1;
            int f = tid + (i & 1) * 256;
            int r = f >> 3, c8 = (f & 7) * 8;
            size_t g = ((size_t)(b * SEQ + r)) * HEAD + c8;
            cpa16(saddr(kv + arr * 2 * 4608 + r * 72 + c8), gs[arr] + g);
        }
    }
    cp_commit();

    float o[8][4];
#pragma unroll
    for (int j = 0; j < 8; ++j)
#pragma unroll
        for (int r = 0; r < 4; ++r) o[j][r] = 0.0f;
    float m_lo = -1e30f, m_hi = -1e30f, l_lo = 0.0f, l_hi = 0.0f;

    const int a_r = warp * 16 + (lane & 7) + ((lane & 8) ? 8 : 0);
    const int a_k8 = (lane & 16) ? 8 : 0;
    const int kb_r = ((lane & 16) ? 8 : 0) + (lane & 7);   // K x4 row-in-16
    const int kb_c8 = (lane & 8) ? 8 : 0;                  // K x4 k-offset
    const int vb_r = ((lane & 8) ? 8 : 0) + (lane & 7);    // V x4t k-row-in-16
    const int vb_c = (lane & 16) ? 8 : 0;                  // V x4t n-offset
    const int grl = q0 + warp * 16 + (lane >> 2);

    for (int t = 0; t < NTILES; ++t) {
        const int buf = t & 1;
        __half* ks_h = kv + buf * 4608;
        __half* ks_l = kv + 2 * 4608 + buf * 4608;
        __half* vs_h = kv + 4 * 4608 + buf * 4608;

        __syncthreads();
        if (t + 1 < NTILES) {
            const __half* gs[3] = {g_Kh, g_Kl, g_Vh};
            int nb = buf ^ 1;
#pragma unroll
            for (int i = 0; i < 6; ++i) {
                int arr = i >> 1;
                int f = tid + (i & 1) * 256;
                int r = f >> 3, c8 = (f & 7) * 8;
                size_t g = ((size_t)(b * SEQ + (t + 1) * 64 + r)) * HEAD + c8;
                cpa16(saddr(kv + arr * 2 * 4608 + nb * 4608 + r * 72 + c8), gs[arr] + g);
            }
            cp_commit();
            cp_wait<1>();
        } else {
            cp_wait<0>();
        }
        __syncthreads();

        // ---- S = Q @ K^T (3 MMAs per 16x8x16 step) ----
        float s[8][4];
#pragma unroll
        for (int j = 0; j < 8; ++j)
#pragma unroll
            for (int r = 0; r < 4; ++r) s[j][r] = 0.0f;

#pragma unroll
        for (int u = 0; u < 4; ++u) {
            unsigned qh[4], ql[4];
            ldm_x4(qh[0], qh[1], qh[2], qh[3], saddr(&qs_h[a_r * 72 + u * 16 + a_k8]));
            ldm_x4(ql[0], ql[1], ql[2], ql[3], saddr(&qs_l[a_r * 72 + u * 16 + a_k8]));
#pragma unroll
            for (int jj = 0; jj < 4; ++jj) {
                unsigned kh0, kh1, kh2, kh3, kl0, kl1, kl2, kl3;
                ldm_x4(kh0, kh1, kh2, kh3,
                       saddr(&ks_h[(jj * 16 + kb_r) * 72 + u * 16 + kb_c8]));
                ldm_x4(kl0, kl1, kl2, kl3,
                       saddr(&ks_l[(jj * 16 + kb_r) * 72 + u * 16 + kb_c8]));
                mma_f16(s[2 * jj], qh, kh0, kh1);
                mma_f16(s[2 * jj], qh, kl0, kl1);
                mma_f16(s[2 * jj], ql, kh0, kh1);
                mma_f16(s[2 * jj + 1], qh, kh2, kh3);
                mma_f16(s[2 * jj + 1], qh, kl2, kl3);
                mma_f16(s[2 * jj + 1], ql, kh2, kh3);
            }
        }

        // ---- mask + online softmax (fp16x2 exp) ----
        const int k0 = t * 64;
        unsigned long long mw_lo =
            *(const unsigned long long*)&g_maskbits[(size_t)grl * 64 + (k0 >> 5)];
        unsigned long long mw_hi =
            *(const unsigned long long*)&g_maskbits[(size_t)(grl + 8) * 64 + (k0 >> 5)];
        float rmax_lo = NEG_INF, rmax_hi = NEG_INF;
#pragma unroll
        for (int j = 0; j < 8; ++j) {
            int cb = j * 8 + (lane & 3) * 2;
            s[j][0] = ((mw_lo >> cb) & 1ull) ? s[j][0] : NEG_INF;
            s[j][1] = ((mw_lo >> (cb + 1)) & 1ull) ? s[j][1] : NEG_INF;
            s[j][2] = ((mw_hi >> cb) & 1ull) ? s[j][2] : NEG_INF;
            s[j][3] = ((mw_hi >> (cb + 1)) & 1ull) ? s[j][3] : NEG_INF;
            rmax_lo = fmaxf(rmax_lo, fmaxf(s[j][0], s[j][1]));
            rmax_hi = fmaxf(rmax_hi, fmaxf(s[j][2], s[j][3]));
        }
        rmax_lo = fmaxf(rmax_lo, __shfl_xor_sync(0xffffffffu, rmax_lo, 1));
        rmax_lo = fmaxf(rmax_lo, __shfl_xor_sync(0xffffffffu, rmax_lo, 2));
        rmax_hi = fmaxf(rmax_hi, __shfl_xor_sync(0xffffffffu, rmax_hi, 1));
        rmax_hi = fmaxf(rmax_hi, __shfl_xor_sync(0xffffffffu, rmax_hi, 2));

        float mnew_lo = fmaxf(m_lo, rmax_lo);
        float mnew_hi = fmaxf(m_hi, rmax_hi);
        float corr_lo = __expf(m_lo - mnew_lo);
        float corr_hi = __expf(m_hi - mnew_hi);
        float nml_lo = -mnew_lo * LOG2E;
        float nml_hi = -mnew_hi * LOG2E;

        unsigned p_lo[8], p_hi[8];
#pragma unroll
        for (int j = 0; j < 8; ++j) {
            p_lo[j] = exp2_pack(fmaf(s[j][0], LOG2E, nml_lo),
                                fmaf(s[j][1], LOG2E, nml_lo));
            p_hi[j] = exp2_pack(fmaf(s[j][2], LOG2E, nml_hi),
                                fmaf(s[j][3], LOG2E, nml_hi));
        }

        m_lo = mnew_lo;  m_hi = mnew_hi;
#pragma unroll
        for (int j = 0; j < 8; ++j) {
            o[j][0] *= corr_lo; o[j][1] *= corr_lo;
            o[j][2] *= corr_hi; o[j][3] *= corr_hi;
        }

        // ---- O += P @ V ; l-sum via ones-MMA ----
        float ls[4] = {0.0f, 0.0f, 0.0f, 0.0f};
#pragma unroll
        for (int u = 0; u < 4; ++u) {
            unsigned pa[4];
            pa[0] = p_lo[2 * u];     pa[1] = p_hi[2 * u];
            pa[2] = p_lo[2 * u + 1]; pa[3] = p_hi[2 * u + 1];
            mma_f16(ls, pa, ONESF16, ONESF16);
#pragma unroll
            for (int jj = 0; jj < 4; ++jj) {
                unsigned v0, v1, v2, v3;
                ldm_x4t(v0, v1, v2, v3,
                        saddr(&vs_h[(u * 16 + vb_r) * 72 + jj * 16 + vb_c]));
                mma_f16(o[2 * jj], pa, v0, v1);
                mma_f16(o[2 * jj + 1], pa, v2, v3);
            }
        }
        l_lo = l_lo * corr_lo + ls[0];
        l_hi = l_hi * corr_hi + ls[2];
    }

    // epilogue: O /= l
    float inv_lo = 1.0f / l_lo, inv_hi = 1.0f / l_hi;
#pragma unroll
    for (int j = 0; j < 8; ++j) {
        int col = j * 8 + (lane & 3) * 2;
        size_t r0 = (size_t)b * SEQ + grl;
        float2 v0 = {o[j][0] * inv_lo, o[j][1] * inv_lo};
        float2 v1 = {o[j][2] * inv_hi, o[j][3] * inv_hi};
        *(float2*)&out[r0 * HEAD + col] = v0;
        *(float2*)&out[(r0 + 8) * HEAD + col] = v1;
    }
}

// ---------------------------------------------------------------------------
extern "C" void kernel_launch(void* const* d_in, const int* in_sizes, int n_in,
                              void* d_out, int out_size)
{
    const float* x  = (const float*)d_in[0];
    const float* Wq = (const float*)d_in[1];
    const float* bq = (const float*)d_in[2];
    const float* Wk = (const float*)d_in[3];
    const float* bk = (const float*)d_in[4];
    const float* Wv = (const float*)d_in[5];
    const float* bv = (const float*)d_in[6];
    const int* mask = (const int*)d_in[7];
    float* out = (float*)d_out;

    cudaFuncSetAttribute(attn_kernel,
                         cudaFuncAttributeMaxDynamicSharedMemorySize, ATTN_SMEM);

    qkv_mask_kernel<<<QKV_CTAS + MASK_CTAS, 256>>>(x, Wq, bq, Wk, bk, Wv, bv, mask);
    attn_kernel<<<dim3(SEQ / 128, BATCH), 256, ATTN_SMEM>>>(out);
}